// round 15
// baseline (speedup 1.0000x reference)
#include <cuda_runtime.h>

#define FULL 0xffffffffu
typedef unsigned long long u64;

// ---------- packed f32x2 helpers ----------
__device__ __forceinline__ u64 pk(float lo, float hi) {
    u64 r; asm("mov.b64 %0, {%1,%2};" : "=l"(r) : "f"(lo), "f"(hi)); return r;
}
__device__ __forceinline__ u64 pk2(float v) { return pk(v, v); }
__device__ __forceinline__ void upk(u64 a, float& lo, float& hi) {
    asm("mov.b64 {%0,%1}, %2;" : "=f"(lo), "=f"(hi) : "l"(a));
}
__device__ __forceinline__ u64 fma2(u64 a, u64 b, u64 c) {
    u64 d; asm("fma.rn.f32x2 %0, %1, %2, %3;" : "=l"(d) : "l"(a), "l"(b), "l"(c)); return d;
}
__device__ __forceinline__ u64 mul2(u64 a, u64 b) {
    u64 d; asm("mul.rn.f32x2 %0, %1, %2;" : "=l"(d) : "l"(a), "l"(b)); return d;
}
__device__ __forceinline__ u64 add2(u64 a, u64 b) {
    u64 d; asm("add.rn.f32x2 %0, %1, %2;" : "=l"(d) : "l"(a), "l"(b)); return d;
}
__device__ __forceinline__ u64 sub2(u64 a, u64 b) {
    u64 d; asm("sub.rn.f32x2 %0, %1, %2;" : "=l"(d) : "l"(a), "l"(b)); return d;
}
__device__ __forceinline__ u64 swp(u64 a) { float l, h; upk(a, l, h); return pk(h, l); }
__device__ __forceinline__ u64 shfx(u64 a, int m) {
    float l, h; upk(a, l, h);
    return pk(__shfl_xor_sync(FULL, l, m), __shfl_xor_sync(FULL, h, m));
}
__device__ __forceinline__ u64 shfi(u64 a, int s) {
    float l, h; upk(a, l, h);
    return pk(__shfl_sync(FULL, l, s), __shfl_sync(FULL, h, s));
}

// Per gate (layer*8+wire): 6-u64 stride, 5 pre-packed constants of fused
// C = Rz*Ry*Rx (SU(2) row 0):
// [0]=(C00r,C00i) [1]=(C01r,C01i) [2]=(C01i,-C01r) [3]=(C00i,-C00r)
// [4]=(-C00r,-C00i) [5]=pad  (pairs [0,1] and [2,3] are 16B-aligned)
__device__ u64 g_Gp[48 * 6];

__global__ void precompute_G(const float* __restrict__ w) {
    int tid = threadIdx.x;
    if (tid >= 48) return;
    float c0, s0, c1, s1, cz, sz;
    sincosf(0.5f * w[tid * 3 + 0], &s0, &c0);   // Rx
    sincosf(0.5f * w[tid * 3 + 1], &s1, &c1);   // Ry
    sincosf(0.5f * w[tid * 3 + 2], &sz, &cz);   // Rz
    float A00r = c1 * c0,  A00i = s1 * s0;
    float A01r = -s1 * c0, A01i = -c1 * s0;
    float C00r = cz * A00r + sz * A00i;
    float C00i = cz * A00i - sz * A00r;
    float C01r = cz * A01r + sz * A01i;
    float C01i = cz * A01i - sz * A01r;
    g_Gp[tid * 6 + 0] = pk(C00r, C00i);
    g_Gp[tid * 6 + 1] = pk(C01r, C01i);
    g_Gp[tid * 6 + 2] = pk(C01i, -C01r);
    g_Gp[tid * 6 + 3] = pk(C00i, -C00r);
    g_Gp[tid * 6 + 4] = pk(-C00r, -C00i);
    g_Gp[tid * 6 + 5] = 0ull;
}

// TWO elements per warp, one per HALF-WARP (16 lanes each). A thread holds 16
// amplitudes of ONE element. Amp index a: half-lane bits 3..0 = wires 0..3;
// local t bits 3..0 = wires 4,5,6,7. u64 j = t>>1 (j bit2=wire4, bit1=wire5,
// bit0=wire6); packed half = wire7. pr[j]=(re[2j],re[2j+1]), pi[j] same.
// State carries sqrt(pi) so <Z> emerges pre-scaled by pi.
__global__ void __launch_bounds__(128, 9) qnn_kernel(const float* __restrict__ x,
                                                     float* __restrict__ out, int NE2) {
    __shared__ u64 sG[48 * 6];
    for (int k = threadIdx.x; k < 48 * 6; k += 128) sG[k] = g_Gp[k];
    __syncthreads();

    int warp = (blockIdx.x * blockDim.x + threadIdx.x) >> 5;
    int lane = threadIdx.x & 31;
    if (warp >= NE2) return;
    int hl = lane & 15;                      // half-lane
    int elem = warp * 2 + (lane >> 4);       // this thread's element

    float se, ce, so, co;
    __sincosf(0.5f * x[2 * elem + 0], &se, &ce);  // RX enc (even wires)
    __sincosf(0.5f * x[2 * elem + 1], &so, &co);  // RY enc (odd wires)
    u64 ce2 = pk2(ce), se2 = pk2(se), co2 = pk2(co), so2 = pk2(so);

    // Fused gate matrix M = C*E(x): packed m00=(m00r,m00i), m01=(m01r,m01i).
#define GATE_M(g, wire, m00p, m01p)                                        \
    {                                                                      \
        ulonglong2 gxy = *reinterpret_cast<const ulonglong2*>(&sG[(g) * 6]); \
        if (((wire) & 1) == 0) {   /* RX */                                \
            ulonglong2 gzw = *reinterpret_cast<const ulonglong2*>(&sG[(g) * 6 + 2]); \
            m00p = fma2(ce2, gxy.x, mul2(se2, gzw.x));                     \
            m01p = fma2(ce2, gxy.y, mul2(se2, gzw.y));                     \
        } else {                   /* RY */                                \
            u64 nGx = sG[(g) * 6 + 4];                                     \
            m00p = fma2(co2, gxy.x, mul2(so2, gxy.y));                     \
            m01p = fma2(co2, gxy.y, mul2(so2, nGx));                       \
        }                                                                  \
    }

    u64 pr[8], pi[8];

    // 4-bit lane perm for composed CNOT(0,1),(1,2),(2,3) (within half-warp)
    int src4 = hl;
    src4 ^= (src4 >> 1) & 1;
    src4 ^= (src4 >> 1) & 2;
    src4 ^= (src4 >> 1) & 4;
    const int srcF = (lane & 16) | src4;
    const bool ctl34 = (hl & 1) != 0;        // CNOT(3,4) control (post-perm wire3)

    // ---------- layer 0: product state built directly from |0..0> ----------
    {
        float g0r[8], g0i[8], g1r[8], g1i[8];   // column 0: m00 and m10=-conj(m01)
#pragma unroll
        for (int wv = 0; wv < 8; wv++) {
            u64 m00p, m01p;
            GATE_M(wv, wv, m00p, m01p);
            float r0, i0, r1, i1;
            upk(m00p, r0, i0); upk(m01p, r1, i1);
            g0r[wv] = r0;  g0i[wv] = i0;
            g1r[wv] = -r1; g1i[wv] = i1;
        }
        float cr = 1.7724538509055159f, ci = 0.f;   // sqrt(pi) folded in
#pragma unroll
        for (int wv = 0; wv < 4; wv++) {
            bool b = (hl >> (3 - wv)) & 1;
            float fr = b ? g1r[wv] : g0r[wv];
            float fi = b ? g1i[wv] : g0i[wv];
            float nr = cr * fr - ci * fi;
            float ni = cr * fi + ci * fr;
            cr = nr; ci = ni;
        }
        // expand register wires 4,5,6,7 into 16 amps
        float d0r = cr * g0r[4] - ci * g0i[4], d0i = cr * g0i[4] + ci * g0r[4];
        float d1r = cr * g1r[4] - ci * g1i[4], d1i = cr * g1i[4] + ci * g1r[4];
        float er[4], ei[4];
        er[0] = d0r * g0r[5] - d0i * g0i[5]; ei[0] = d0r * g0i[5] + d0i * g0r[5];
        er[1] = d0r * g1r[5] - d0i * g1i[5]; ei[1] = d0r * g1i[5] + d0i * g1r[5];
        er[2] = d1r * g0r[5] - d1i * g0i[5]; ei[2] = d1r * g0i[5] + d1i * g0r[5];
        er[3] = d1r * g1r[5] - d1i * g1i[5]; ei[3] = d1r * g1i[5] + d1i * g1r[5];
        float fr8[8], fi8[8];
#pragma unroll
        for (int k = 0; k < 4; k++) {
            fr8[2*k]   = er[k] * g0r[6] - ei[k] * g0i[6];
            fi8[2*k]   = er[k] * g0i[6] + ei[k] * g0r[6];
            fr8[2*k+1] = er[k] * g1r[6] - ei[k] * g1i[6];
            fi8[2*k+1] = er[k] * g1i[6] + ei[k] * g1r[6];
        }
#pragma unroll
        for (int j = 0; j < 8; j++) {
            float alr = fr8[j] * g0r[7] - fi8[j] * g0i[7];
            float ali = fr8[j] * g0i[7] + fi8[j] * g0r[7];
            float ahr = fr8[j] * g1r[7] - fi8[j] * g1i[7];
            float ahi = fr8[j] * g1i[7] + fi8[j] * g1r[7];
            pr[j] = pk(alr, ahr);
            pi[j] = pk(ali, ahi);
        }
        // layer-0 lane perm (standalone)
#pragma unroll
        for (int j = 0; j < 8; j++) {
            pr[j] = shfi(pr[j], srcF);
            pi[j] = shfi(pi[j], srcF);
        }
    }

    // register-level CNOT tail: (3,4) predicated, (4,5)&(5,6) renames, (6,7) half-swap
#define REG_CNOTS()                                                          \
    {                                                                        \
        _Pragma("unroll")                                                    \
        for (int k = 0; k < 4; k++) {                                        \
            u64 a = pr[k], b = pr[k + 4];                                    \
            pr[k] = ctl34 ? b : a; pr[k + 4] = ctl34 ? a : b;                \
            u64 c = pi[k], d = pi[k + 4];                                    \
            pi[k] = ctl34 ? d : c; pi[k + 4] = ctl34 ? c : d;                \
        }                                                                    \
        { u64 t_;                                                            \
          t_ = pr[4]; pr[4] = pr[6]; pr[6] = t_;                             \
          t_ = pi[4]; pi[4] = pi[6]; pi[6] = t_;                             \
          t_ = pr[5]; pr[5] = pr[7]; pr[7] = t_;                             \
          t_ = pi[5]; pi[5] = pi[7]; pi[7] = t_; }                           \
        { u64 t_;                                                            \
          t_ = pr[2]; pr[2] = pr[3]; pr[3] = t_;                             \
          t_ = pi[2]; pi[2] = pi[3]; pi[3] = t_;                             \
          t_ = pr[6]; pr[6] = pr[7]; pr[7] = t_;                             \
          t_ = pi[6]; pi[6] = pi[7]; pi[7] = t_; }                           \
        pr[1] = swp(pr[1]); pr[3] = swp(pr[3]);                              \
        pr[5] = swp(pr[5]); pr[7] = swp(pr[7]);                              \
        pi[1] = swp(pi[1]); pi[3] = swp(pi[3]);                              \
        pi[5] = swp(pi[5]); pi[7] = swp(pi[7]);                              \
    }

    REG_CNOTS();

    // ---------- layers 1..5 ----------
#pragma unroll
    for (int layer = 1; layer < 6; layer++) {
#pragma unroll
        for (int wire = 0; wire < 8; wire++) {
            u64 m00p, m01p;
            GATE_M(layer * 8 + wire, wire, m00p, m01p);
            float m00r, m00i, m01r, m01i;
            upk(m00p, m00r, m00i); upk(m01p, m01r, m01i);

            if (wire < 3) {
                // lane-level butterfly via shfl.xor (within half-warp)
                const int lm = 8 >> wire;
                bool neg = (hl & lm) != 0;
                float Piv = neg ? -m00i : m00i;
                float Qrv = neg ? -m01r : m01r;
                u64 Pr2 = pk2(m00r), Pi2 = pk2(Piv), nPi2 = pk2(-Piv);
                u64 Qr2 = pk2(Qrv), Qi2 = pk2(m01i), nQi2 = pk2(-m01i);
#pragma unroll
                for (int j = 0; j < 8; j++) {
                    u64 opr = shfx(pr[j], lm);
                    u64 opi = shfx(pi[j], lm);
                    u64 nr = fma2(Pr2, pr[j], fma2(nPi2, pi[j], fma2(Qr2, opr, mul2(nQi2, opi))));
                    u64 ni = fma2(Pi2, pr[j], fma2(Pr2, pi[j], fma2(Qi2, opr, mul2(Qr2, opi))));
                    pr[j] = nr; pi[j] = ni;
                }
            } else if (wire == 3) {
                // wire-3 gate FUSED with the lane CNOT perm (perm commutes with
                // the register-local wires 4..7 gates).
                bool negf = (srcF & 1) != 0;
                float Piv = negf ? -m00i : m00i;
                float Qrv = negf ? -m01r : m01r;
                u64 Pr2 = pk2(m00r), Pi2 = pk2(Piv), nPi2 = pk2(-Piv);
                u64 Qr2 = pk2(Qrv), Qi2 = pk2(m01i), nQi2 = pk2(-m01i);
#pragma unroll
                for (int j = 0; j < 8; j++) {
                    u64 ar = shfi(pr[j], srcF);
                    u64 ai = shfi(pi[j], srcF);
                    u64 br = shfi(pr[j], srcF ^ 1);
                    u64 bi = shfi(pi[j], srcF ^ 1);
                    u64 nr = fma2(Pr2, ar, fma2(nPi2, ai, fma2(Qr2, br, mul2(nQi2, bi))));
                    u64 ni = fma2(Pi2, ar, fma2(Pr2, ai, fma2(Qi2, br, mul2(Qr2, bi))));
                    pr[j] = nr; pi[j] = ni;
                }
            } else if (wire < 7) {
                // inter-register butterfly: wire4 off=4, wire5 off=2, wire6 off=1
                u64 r00 = pk2(m00r), i00 = pk2(m00i), ni00 = pk2(-m00i);
                u64 r01 = pk2(m01r), nr01 = pk2(-m01r), i01 = pk2(m01i), ni01 = pk2(-m01i);
                const int off = (wire == 4) ? 4 : ((wire == 5) ? 2 : 1);
#pragma unroll
                for (int j = 0; j < 8; j++) {
                    if (j & off) continue;
                    int k = j | off;
                    u64 pA = pr[j], qA = pi[j], pB = pr[k], qB = pi[k];
                    pr[j] = fma2(r00, pA, fma2(ni00, qA, fma2(r01, pB, mul2(ni01, qB))));
                    pi[j] = fma2(i00, pA, fma2(r00, qA, fma2(i01, pB, mul2(r01, qB))));
                    pr[k] = fma2(nr01, pA, fma2(ni01, qA, fma2(r00, pB, mul2(i00, qB))));
                    pi[k] = fma2(i01, pA, fma2(nr01, qA, fma2(ni00, pB, mul2(r00, qB))));
                }
            } else {
                // wire7: intra-register butterfly with half-swaps
                u64 A = pk2(m00r);
                u64 Bc = pk(m01r, -m01r);
                u64 Cc = pk(-m00i, m00i);
                u64 D = pk2(-m01i);
                u64 E = pk(m00i, -m00i);
                u64 F = pk2(m01i);
#pragma unroll
                for (int j = 0; j < 8; j++) {
                    u64 spr = swp(pr[j]), spi = swp(pi[j]);
                    u64 nr = fma2(A, pr[j], fma2(Bc, spr, fma2(Cc, pi[j], mul2(D, spi))));
                    u64 ni = fma2(E, pr[j], fma2(F, spr, fma2(A, pi[j], mul2(Bc, spi))));
                    pr[j] = nr; pi[j] = ni;
                }
            }
        }
        REG_CNOTS();
    }

    // ---------- expectation values (pre-scaled by pi), packed u64 trees ----------
    u64 q[8];
#pragma unroll
    for (int j = 0; j < 8; j++)
        q[j] = fma2(pr[j], pr[j], mul2(pi[j], pi[j]));

    // pairwise trees (j bit2 = wire4, bit1 = wire5, bit0 = wire6; half = wire7)
    u64 t01 = add2(q[0], q[1]), t23 = add2(q[2], q[3]);
    u64 t45 = add2(q[4], q[5]), t67 = add2(q[6], q[7]);
    u64 A4 = add2(t01, t23), B4 = add2(t45, t67);
    u64 S  = add2(A4, B4);                        // grand packed sum
    u64 D4 = sub2(A4, B4);                        // wire4 sign (j bit2)
    u64 D5 = sub2(add2(t01, t45), add2(t23, t67)); // wire5 sign (j bit1)
    u64 D6 = add2(add2(sub2(q[0], q[1]), sub2(q[2], q[3])),
                  add2(sub2(q[4], q[5]), sub2(q[6], q[7]))); // wire6 (j bit0)

    float sl, sh, d4l, d4h, d5l, d5h, d6l, d6h;
    upk(S, sl, sh); upk(D4, d4l, d4h); upk(D5, d5l, d5h); upk(D6, d6l, d6h);
    float tot = sl + sh;        // total probability (pi-scaled)
    float ev7 = sl - sh;        // wire7 = packed half
    float ev4 = d4l + d4h;
    float ev5 = d5l + d5h;
    float ev6 = d6l + d6h;

    // 4-step Walsh-Hadamard on tot within the half-warp: X(k) at hl=k;
    // ev_i (wires 0..3) = X(1<<(3-i)). Plain-add butterflies for ev4..7.
#pragma unroll
    for (int b = 0; b < 4; b++) {
        const int m = 1 << b;
        float o = __shfl_xor_sync(FULL, tot, m);
        tot = (lane & m) ? (o - tot) : (o + tot);
        ev4 += __shfl_xor_sync(FULL, ev4, m);
        ev5 += __shfl_xor_sync(FULL, ev5, m);
        ev6 += __shfl_xor_sync(FULL, ev6, m);
        ev7 += __shfl_xor_sync(FULL, ev7, m);
    }

    float* o = out + elem * 8;
    if (hl == 8) o[0] = tot;
    if (hl == 4) o[1] = tot;
    if (hl == 2) o[2] = tot;
    if (hl == 1) o[3] = tot;
    if (hl == 0) {
        o[4] = ev4;
        o[5] = ev5;
        o[6] = ev6;
        o[7] = ev7;
    }
#undef GATE_M
#undef REG_CNOTS
}

extern "C" void kernel_launch(void* const* d_in, const int* in_sizes, int n_in,
                              void* d_out, int out_size) {
    const float* x = (const float*)d_in[0];   // [B, 2]
    const float* w = (const float*)d_in[1];   // [6, 8, 3]
    float* out = (float*)d_out;               // [B, 8]
    int B = in_sizes[0] / 2;
    int NE2 = B / 2;                          // warps (2 elements per warp)

    precompute_G<<<1, 64>>>(w);
    int threads = 128;
    int blocks = (NE2 * 32 + threads - 1) / threads;
    qnn_kernel<<<blocks, threads>>>(x, out, NE2);
}

// round 16
// speedup vs baseline: 1.0172x; 1.0172x over previous
#include <cuda_runtime.h>

#define FULL 0xffffffffu
typedef unsigned long long u64;

// ---------- packed f32x2 helpers ----------
__device__ __forceinline__ u64 pk(float lo, float hi) {
    u64 r; asm("mov.b64 %0, {%1,%2};" : "=l"(r) : "f"(lo), "f"(hi)); return r;
}
__device__ __forceinline__ u64 pk2(float v) { return pk(v, v); }
__device__ __forceinline__ void upk(u64 a, float& lo, float& hi) {
    asm("mov.b64 {%0,%1}, %2;" : "=f"(lo), "=f"(hi) : "l"(a));
}
__device__ __forceinline__ u64 fma2(u64 a, u64 b, u64 c) {
    u64 d; asm("fma.rn.f32x2 %0, %1, %2, %3;" : "=l"(d) : "l"(a), "l"(b), "l"(c)); return d;
}
__device__ __forceinline__ u64 mul2(u64 a, u64 b) {
    u64 d; asm("mul.rn.f32x2 %0, %1, %2;" : "=l"(d) : "l"(a), "l"(b)); return d;
}
__device__ __forceinline__ u64 add2(u64 a, u64 b) {
    u64 d; asm("add.rn.f32x2 %0, %1, %2;" : "=l"(d) : "l"(a), "l"(b)); return d;
}
__device__ __forceinline__ u64 sub2(u64 a, u64 b) {
    u64 d; asm("sub.rn.f32x2 %0, %1, %2;" : "=l"(d) : "l"(a), "l"(b)); return d;
}
__device__ __forceinline__ u64 swp(u64 a) { float l, h; upk(a, l, h); return pk(h, l); }
__device__ __forceinline__ u64 shfx(u64 a, int m) {
    float l, h; upk(a, l, h);
    return pk(__shfl_xor_sync(FULL, l, m), __shfl_xor_sync(FULL, h, m));
}
__device__ __forceinline__ u64 shfi(u64 a, int s) {
    float l, h; upk(a, l, h);
    return pk(__shfl_sync(FULL, l, s), __shfl_sync(FULL, h, s));
}

// Per gate (layer*8+wire): 4 pre-packed u64 of fused C = Rz*Ry*Rx (SU(2) row 0):
// [0]=(C00r,C00i) [1]=(C01r,C01i) [2]=(C01i,-C01r) [3]=(C00i,-C00r)
__device__ u64 g_Gp[48 * 4];

__global__ void precompute_G(const float* __restrict__ w) {
    int tid = threadIdx.x;
    if (tid >= 48) return;
    float c0, s0, c1, s1, cz, sz;
    sincosf(0.5f * w[tid * 3 + 0], &s0, &c0);   // Rx
    sincosf(0.5f * w[tid * 3 + 1], &s1, &c1);   // Ry
    sincosf(0.5f * w[tid * 3 + 2], &sz, &cz);   // Rz
    float A00r = c1 * c0,  A00i = s1 * s0;
    float A01r = -s1 * c0, A01i = -c1 * s0;
    float C00r = cz * A00r + sz * A00i;
    float C00i = cz * A00i - sz * A00r;
    float C01r = cz * A01r + sz * A01i;
    float C01i = cz * A01i - sz * A01r;
    g_Gp[tid * 4 + 0] = pk(C00r, C00i);
    g_Gp[tid * 4 + 1] = pk(C01r, C01i);
    g_Gp[tid * 4 + 2] = pk(C01i, -C01r);
    g_Gp[tid * 4 + 3] = pk(C00i, -C00r);
}

// TWO elements per warp, one per HALF-WARP (16 lanes each). A thread holds 16
// amplitudes of ONE element. Amp index a: half-lane bits 3..0 = wires 0..3;
// local t bits 3..0 = wires 4,5,6,7. u64 j = t>>1 (j bit2=wire4, bit1=wire5,
// bit0=wire6); packed half = wire7. pr[j]=(re[2j],re[2j+1]), pi[j] same.
// State carries sqrt(pi) so <Z> emerges pre-scaled by pi.
__global__ void __launch_bounds__(128, 8) qnn_kernel(const float2* __restrict__ x2,
                                                     float* __restrict__ out, int NE2) {
    __shared__ u64 sG[48 * 4];
    for (int k = threadIdx.x; k < 48 * 4; k += 128) sG[k] = g_Gp[k];
    __syncthreads();

    int warp = (blockIdx.x * blockDim.x + threadIdx.x) >> 5;
    int lane = threadIdx.x & 31;
    if (warp >= NE2) return;
    int hl = lane & 15;                      // half-lane
    int elem = warp * 2 + (lane >> 4);       // this thread's element

    float2 xv = x2[elem];
    float se, ce, so, co;
    __sincosf(0.5f * xv.x, &se, &ce);  // RX enc (even wires)
    __sincosf(0.5f * xv.y, &so, &co);  // RY enc (odd wires)
    u64 ce2 = pk2(ce), se2 = pk2(se), co2 = pk2(co), so2 = pk2(so), nso2 = pk2(-so);

    // Fused gate matrix M = C*E(x): packed m00=(m00r,m00i), m01=(m01r,m01i).
#define GATE_M(g, wire, m00p, m01p)                                        \
    {                                                                      \
        ulonglong2 gxy = *reinterpret_cast<const ulonglong2*>(&sG[(g) * 4]); \
        if (((wire) & 1) == 0) {   /* RX */                                \
            ulonglong2 gzw = *reinterpret_cast<const ulonglong2*>(&sG[(g) * 4 + 2]); \
            m00p = fma2(ce2, gxy.x, mul2(se2, gzw.x));                     \
            m01p = fma2(ce2, gxy.y, mul2(se2, gzw.y));                     \
        } else {                   /* RY */                                \
            m00p = fma2(co2, gxy.x, mul2(so2, gxy.y));                     \
            m01p = fma2(co2, gxy.y, mul2(nso2, gxy.x));                    \
        }                                                                  \
    }

    u64 pr[8], pi[8];

    // 4-bit lane perm for composed CNOT(0,1),(1,2),(2,3) (within half-warp)
    int src4 = hl;
    src4 ^= (src4 >> 1) & 1;
    src4 ^= (src4 >> 1) & 2;
    src4 ^= (src4 >> 1) & 4;
    const int srcF = (lane & 16) | src4;
    const int srcF2 = srcF ^ 1;
    const bool negf = (src4 & 1) != 0;       // wire-3 role bit at src
    const bool ctl34 = (hl & 1) != 0;        // CNOT(3,4) control (post-perm wire3)

    // ---------- layer 0: product state built directly from |0..0> ----------
    {
        float g0r[8], g0i[8], g1r[8], g1i[8];   // column 0: m00 and m10=-conj(m01)
#pragma unroll
        for (int wv = 0; wv < 8; wv++) {
            u64 m00p, m01p;
            GATE_M(wv, wv, m00p, m01p);
            float r0, i0, r1, i1;
            upk(m00p, r0, i0); upk(m01p, r1, i1);
            g0r[wv] = r0;  g0i[wv] = i0;
            g1r[wv] = -r1; g1i[wv] = i1;
        }
        float cr = 1.7724538509055159f, ci = 0.f;   // sqrt(pi) folded in
#pragma unroll
        for (int wv = 0; wv < 4; wv++) {
            bool b = (hl >> (3 - wv)) & 1;
            float fr = b ? g1r[wv] : g0r[wv];
            float fi = b ? g1i[wv] : g0i[wv];
            float nr = cr * fr - ci * fi;
            float ni = cr * fi + ci * fr;
            cr = nr; ci = ni;
        }
        // expand register wires 4,5,6,7 into 16 amps
        float d0r = cr * g0r[4] - ci * g0i[4], d0i = cr * g0i[4] + ci * g0r[4];
        float d1r = cr * g1r[4] - ci * g1i[4], d1i = cr * g1i[4] + ci * g1r[4];
        float er[4], ei[4];
        er[0] = d0r * g0r[5] - d0i * g0i[5]; ei[0] = d0r * g0i[5] + d0i * g0r[5];
        er[1] = d0r * g1r[5] - d0i * g1i[5]; ei[1] = d0r * g1i[5] + d0i * g1r[5];
        er[2] = d1r * g0r[5] - d1i * g0i[5]; ei[2] = d1r * g0i[5] + d1i * g0r[5];
        er[3] = d1r * g1r[5] - d1i * g1i[5]; ei[3] = d1r * g1i[5] + d1i * g1r[5];
        float fr8[8], fi8[8];
#pragma unroll
        for (int k = 0; k < 4; k++) {
            fr8[2*k]   = er[k] * g0r[6] - ei[k] * g0i[6];
            fi8[2*k]   = er[k] * g0i[6] + ei[k] * g0r[6];
            fr8[2*k+1] = er[k] * g1r[6] - ei[k] * g1i[6];
            fi8[2*k+1] = er[k] * g1i[6] + ei[k] * g1r[6];
        }
#pragma unroll
        for (int j = 0; j < 8; j++) {
            float alr = fr8[j] * g0r[7] - fi8[j] * g0i[7];
            float ali = fr8[j] * g0i[7] + fi8[j] * g0r[7];
            float ahr = fr8[j] * g1r[7] - fi8[j] * g1i[7];
            float ahi = fr8[j] * g1i[7] + fi8[j] * g1r[7];
            pr[j] = pk(alr, ahr);
            pi[j] = pk(ali, ahi);
        }
        // layer-0 lane perm (standalone)
#pragma unroll
        for (int j = 0; j < 8; j++) {
            pr[j] = shfi(pr[j], srcF);
            pi[j] = shfi(pi[j], srcF);
        }
    }

    // register-level CNOT tail: (3,4) predicated, (4,5)&(5,6) renames, (6,7) half-swap
#define REG_CNOTS()                                                          \
    {                                                                        \
        _Pragma("unroll")                                                    \
        for (int k = 0; k < 4; k++) {                                        \
            u64 a = pr[k], b = pr[k + 4];                                    \
            pr[k] = ctl34 ? b : a; pr[k + 4] = ctl34 ? a : b;                \
            u64 c = pi[k], d = pi[k + 4];                                    \
            pi[k] = ctl34 ? d : c; pi[k + 4] = ctl34 ? c : d;                \
        }                                                                    \
        { u64 t_;                                                            \
          t_ = pr[4]; pr[4] = pr[6]; pr[6] = t_;                             \
          t_ = pi[4]; pi[4] = pi[6]; pi[6] = t_;                             \
          t_ = pr[5]; pr[5] = pr[7]; pr[7] = t_;                             \
          t_ = pi[5]; pi[5] = pi[7]; pi[7] = t_; }                           \
        { u64 t_;                                                            \
          t_ = pr[2]; pr[2] = pr[3]; pr[3] = t_;                             \
          t_ = pi[2]; pi[2] = pi[3]; pi[3] = t_;                             \
          t_ = pr[6]; pr[6] = pr[7]; pr[7] = t_;                             \
          t_ = pi[6]; pi[6] = pi[7]; pi[7] = t_; }                           \
        pr[1] = swp(pr[1]); pr[3] = swp(pr[3]);                              \
        pr[5] = swp(pr[5]); pr[7] = swp(pr[7]);                              \
        pi[1] = swp(pi[1]); pi[3] = swp(pi[3]);                              \
        pi[5] = swp(pi[5]); pi[7] = swp(pi[7]);                              \
    }

    REG_CNOTS();

    // ---------- layers 1..5 ----------
#pragma unroll
    for (int layer = 1; layer < 6; layer++) {
#pragma unroll
        for (int wire = 0; wire < 8; wire++) {
            u64 m00p, m01p;
            GATE_M(layer * 8 + wire, wire, m00p, m01p);
            float m00r, m00i, m01r, m01i;
            upk(m00p, m00r, m00i); upk(m01p, m01r, m01i);

            if (wire < 3) {
                // lane-level butterfly via shfl.xor (within half-warp)
                const int lm = 8 >> wire;
                bool neg = (hl & lm) != 0;
                float Piv = neg ? -m00i : m00i;
                float Qrv = neg ? -m01r : m01r;
                u64 Pr2 = pk2(m00r), Pi2 = pk2(Piv), nPi2 = pk2(-Piv);
                u64 Qr2 = pk2(Qrv), Qi2 = pk2(m01i), nQi2 = pk2(-m01i);
#pragma unroll
                for (int j = 0; j < 8; j++) {
                    u64 opr = shfx(pr[j], lm);
                    u64 opi = shfx(pi[j], lm);
                    u64 nr = fma2(Pr2, pr[j], fma2(nPi2, pi[j], fma2(Qr2, opr, mul2(nQi2, opi))));
                    u64 ni = fma2(Pi2, pr[j], fma2(Pr2, pi[j], fma2(Qi2, opr, mul2(Qr2, opi))));
                    pr[j] = nr; pi[j] = ni;
                }
            } else if (wire == 3) {
                // wire-3 gate FUSED with the lane CNOT perm (perm commutes with
                // the register-local wires 4..7 gates).
                float Piv = negf ? -m00i : m00i;
                float Qrv = negf ? -m01r : m01r;
                u64 Pr2 = pk2(m00r), Pi2 = pk2(Piv), nPi2 = pk2(-Piv);
                u64 Qr2 = pk2(Qrv), Qi2 = pk2(m01i), nQi2 = pk2(-m01i);
#pragma unroll
                for (int j = 0; j < 8; j++) {
                    u64 ar = shfi(pr[j], srcF);
                    u64 ai = shfi(pi[j], srcF);
                    u64 br = shfi(pr[j], srcF2);
                    u64 bi = shfi(pi[j], srcF2);
                    u64 nr = fma2(Pr2, ar, fma2(nPi2, ai, fma2(Qr2, br, mul2(nQi2, bi))));
                    u64 ni = fma2(Pi2, ar, fma2(Pr2, ai, fma2(Qi2, br, mul2(Qr2, bi))));
                    pr[j] = nr; pi[j] = ni;
                }
            } else if (wire < 7) {
                // inter-register butterfly: wire4 off=4, wire5 off=2, wire6 off=1
                u64 r00 = pk2(m00r), i00 = pk2(m00i), ni00 = pk2(-m00i);
                u64 r01 = pk2(m01r), nr01 = pk2(-m01r), i01 = pk2(m01i), ni01 = pk2(-m01i);
                const int off = (wire == 4) ? 4 : ((wire == 5) ? 2 : 1);
#pragma unroll
                for (int j = 0; j < 8; j++) {
                    if (j & off) continue;
                    int k = j | off;
                    u64 pA = pr[j], qA = pi[j], pB = pr[k], qB = pi[k];
                    pr[j] = fma2(r00, pA, fma2(ni00, qA, fma2(r01, pB, mul2(ni01, qB))));
                    pi[j] = fma2(i00, pA, fma2(r00, qA, fma2(i01, pB, mul2(r01, qB))));
                    pr[k] = fma2(nr01, pA, fma2(ni01, qA, fma2(r00, pB, mul2(i00, qB))));
                    pi[k] = fma2(i01, pA, fma2(nr01, qA, fma2(ni00, pB, mul2(r00, qB))));
                }
            } else {
                // wire7: intra-register butterfly with half-swaps
                u64 A = pk2(m00r);
                u64 Bc = pk(m01r, -m01r);
                u64 Cc = pk(-m00i, m00i);
                u64 D = pk2(-m01i);
                u64 E = pk(m00i, -m00i);
                u64 F = pk2(m01i);
#pragma unroll
                for (int j = 0; j < 8; j++) {
                    u64 spr = swp(pr[j]), spi = swp(pi[j]);
                    u64 nr = fma2(A, pr[j], fma2(Bc, spr, fma2(Cc, pi[j], mul2(D, spi))));
                    u64 ni = fma2(E, pr[j], fma2(F, spr, fma2(A, pi[j], mul2(Bc, spi))));
                    pr[j] = nr; pi[j] = ni;
                }
            }
        }
        REG_CNOTS();
    }

    // ---------- expectation values (pre-scaled by pi), packed u64 trees ----------
    u64 q[8];
#pragma unroll
    for (int j = 0; j < 8; j++)
        q[j] = fma2(pr[j], pr[j], mul2(pi[j], pi[j]));

    // pairwise trees (j bit2 = wire4, bit1 = wire5, bit0 = wire6; half = wire7)
    u64 t01 = add2(q[0], q[1]), t23 = add2(q[2], q[3]);
    u64 t45 = add2(q[4], q[5]), t67 = add2(q[6], q[7]);
    u64 A4 = add2(t01, t23), B4 = add2(t45, t67);
    u64 S  = add2(A4, B4);                        // grand packed sum
    u64 D4 = sub2(A4, B4);                        // wire4 sign (j bit2)
    u64 D5 = sub2(add2(t01, t45), add2(t23, t67)); // wire5 sign (j bit1)
    u64 D6 = add2(add2(sub2(q[0], q[1]), sub2(q[2], q[3])),
                  add2(sub2(q[4], q[5]), sub2(q[6], q[7]))); // wire6 (j bit0)

    float sl, sh, d4l, d4h, d5l, d5h, d6l, d6h;
    upk(S, sl, sh); upk(D4, d4l, d4h); upk(D5, d5l, d5h); upk(D6, d6l, d6h);
    float tot = sl + sh;                 // total probability (pi-scaled)
    u64 e45 = pk(d4l + d4h, d5l + d5h);  // (ev4, ev5) packed
    u64 e67 = pk(d6l + d6h, sl - sh);    // (ev6, ev7) packed

    // 4-step Walsh-Hadamard on tot within the half-warp: X(k) at hl=k;
    // ev_i (wires 0..3) = X(1<<(3-i)). Packed plain-add butterflies for ev4..7.
#pragma unroll
    for (int b = 0; b < 4; b++) {
        const int m = 1 << b;
        float o = __shfl_xor_sync(FULL, tot, m);
        tot = (lane & m) ? (o - tot) : (o + tot);
        e45 = add2(e45, shfx(e45, m));
        e67 = add2(e67, shfx(e67, m));
    }

    float* o = out + elem * 8;
    if (hl == 8) o[0] = tot;
    if (hl == 4) o[1] = tot;
    if (hl == 2) o[2] = tot;
    if (hl == 1) o[3] = tot;
    if (hl == 0) {
        float a4, a5, a6, a7;
        upk(e45, a4, a5); upk(e67, a6, a7);
        o[4] = a4;
        o[5] = a5;
        o[6] = a6;
        o[7] = a7;
    }
#undef GATE_M
#undef REG_CNOTS
}

extern "C" void kernel_launch(void* const* d_in, const int* in_sizes, int n_in,
                              void* d_out, int out_size) {
    const float* x = (const float*)d_in[0];   // [B, 2]
    const float* w = (const float*)d_in[1];   // [6, 8, 3]
    float* out = (float*)d_out;               // [B, 8]
    int B = in_sizes[0] / 2;
    int NE2 = B / 2;                          // warps (2 elements per warp)

    precompute_G<<<1, 64>>>(w);
    int threads = 128;
    int blocks = (NE2 * 32 + threads - 1) / threads;
    qnn_kernel<<<blocks, threads>>>((const float2*)x, out, NE2);
}

// round 17
// speedup vs baseline: 1.0203x; 1.0030x over previous
#include <cuda_runtime.h>

#define FULL 0xffffffffu
typedef unsigned long long u64;

// ---------- packed f32x2 helpers ----------
__device__ __forceinline__ u64 pk(float lo, float hi) {
    u64 r; asm("mov.b64 %0, {%1,%2};" : "=l"(r) : "f"(lo), "f"(hi)); return r;
}
__device__ __forceinline__ u64 pk2(float v) { return pk(v, v); }
__device__ __forceinline__ void upk(u64 a, float& lo, float& hi) {
    asm("mov.b64 {%0,%1}, %2;" : "=f"(lo), "=f"(hi) : "l"(a));
}
__device__ __forceinline__ u64 fma2(u64 a, u64 b, u64 c) {
    u64 d; asm("fma.rn.f32x2 %0, %1, %2, %3;" : "=l"(d) : "l"(a), "l"(b), "l"(c)); return d;
}
__device__ __forceinline__ u64 mul2(u64 a, u64 b) {
    u64 d; asm("mul.rn.f32x2 %0, %1, %2;" : "=l"(d) : "l"(a), "l"(b)); return d;
}
__device__ __forceinline__ u64 add2(u64 a, u64 b) {
    u64 d; asm("add.rn.f32x2 %0, %1, %2;" : "=l"(d) : "l"(a), "l"(b)); return d;
}
__device__ __forceinline__ u64 sub2(u64 a, u64 b) {
    u64 d; asm("sub.rn.f32x2 %0, %1, %2;" : "=l"(d) : "l"(a), "l"(b)); return d;
}
__device__ __forceinline__ u64 swp(u64 a) { float l, h; upk(a, l, h); return pk(h, l); }
// native 64-bit shuffles — nvcc emits 2 SHFLs on the register pair without
// explicit pack/unpack MOVs
__device__ __forceinline__ u64 shfx(u64 a, int m) {
    return __shfl_xor_sync(FULL, a, m);
}
__device__ __forceinline__ u64 shfi(u64 a, int s) {
    return __shfl_sync(FULL, a, s);
}

// Per gate (layer*8+wire): 4 pre-packed u64 of fused C = Rz*Ry*Rx (SU(2) row 0):
// [0]=(C00r,C00i) [1]=(C01r,C01i) [2]=(C01i,-C01r) [3]=(C00i,-C00r)
__device__ u64 g_Gp[48 * 4];

__global__ void precompute_G(const float* __restrict__ w) {
    int tid = threadIdx.x;
    if (tid >= 48) return;
    float c0, s0, c1, s1, cz, sz;
    sincosf(0.5f * w[tid * 3 + 0], &s0, &c0);   // Rx
    sincosf(0.5f * w[tid * 3 + 1], &s1, &c1);   // Ry
    sincosf(0.5f * w[tid * 3 + 2], &sz, &cz);   // Rz
    float A00r = c1 * c0,  A00i = s1 * s0;
    float A01r = -s1 * c0, A01i = -c1 * s0;
    float C00r = cz * A00r + sz * A00i;
    float C00i = cz * A00i - sz * A00r;
    float C01r = cz * A01r + sz * A01i;
    float C01i = cz * A01i - sz * A01r;
    g_Gp[tid * 4 + 0] = pk(C00r, C00i);
    g_Gp[tid * 4 + 1] = pk(C01r, C01i);
    g_Gp[tid * 4 + 2] = pk(C01i, -C01r);
    g_Gp[tid * 4 + 3] = pk(C00i, -C00r);
}

// TWO elements per warp, one per HALF-WARP (16 lanes each). A thread holds 16
// amplitudes of ONE element. Amp index a: half-lane bits 3..0 = wires 0..3;
// local t bits 3..0 = wires 4,5,6,7. u64 j = t>>1 (j bit2=wire4, bit1=wire5,
// bit0=wire6); packed half = wire7. pr[j]=(re[2j],re[2j+1]), pi[j] same.
// State carries sqrt(pi) so <Z> emerges pre-scaled by pi.
__global__ void __launch_bounds__(128, 8) qnn_kernel(const float2* __restrict__ x2,
                                                     float* __restrict__ out, int NE2) {
    __shared__ u64 sG[48 * 4];
    for (int k = threadIdx.x; k < 48 * 4; k += 128) sG[k] = g_Gp[k];
    __syncthreads();

    int warp = (blockIdx.x * blockDim.x + threadIdx.x) >> 5;
    int lane = threadIdx.x & 31;
    if (warp >= NE2) return;
    int hl = lane & 15;                      // half-lane
    int elem = warp * 2 + (lane >> 4);       // this thread's element

    float2 xv = x2[elem];
    float se, ce, so, co;
    __sincosf(0.5f * xv.x, &se, &ce);  // RX enc (even wires)
    __sincosf(0.5f * xv.y, &so, &co);  // RY enc (odd wires)
    u64 ce2 = pk2(ce), se2 = pk2(se), co2 = pk2(co), so2 = pk2(so), nso2 = pk2(-so);

    // Fused gate matrix M = C*E(x): packed m00=(m00r,m00i), m01=(m01r,m01i).
#define GATE_M(g, wire, m00p, m01p)                                        \
    {                                                                      \
        ulonglong2 gxy = *reinterpret_cast<const ulonglong2*>(&sG[(g) * 4]); \
        if (((wire) & 1) == 0) {   /* RX */                                \
            ulonglong2 gzw = *reinterpret_cast<const ulonglong2*>(&sG[(g) * 4 + 2]); \
            m00p = fma2(ce2, gxy.x, mul2(se2, gzw.x));                     \
            m01p = fma2(ce2, gxy.y, mul2(se2, gzw.y));                     \
        } else {                   /* RY */                                \
            m00p = fma2(co2, gxy.x, mul2(so2, gxy.y));                     \
            m01p = fma2(co2, gxy.y, mul2(nso2, gxy.x));                    \
        }                                                                  \
    }

    u64 pr[8], pi[8];

    // 4-bit lane perm for composed CNOT(0,1),(1,2),(2,3) (within half-warp)
    int src4 = hl;
    src4 ^= (src4 >> 1) & 1;
    src4 ^= (src4 >> 1) & 2;
    src4 ^= (src4 >> 1) & 4;
    const int srcF = (lane & 16) | src4;
    const int srcF2 = srcF ^ 1;
    const bool negf = (src4 & 1) != 0;       // wire-3 role bit at src
    const bool ctl34 = (hl & 1) != 0;        // CNOT(3,4) control (post-perm wire3)

    // ---------- layer 0: product state built directly from |0..0> ----------
    {
        float g0r[8], g0i[8], g1r[8], g1i[8];   // column 0: m00 and m10=-conj(m01)
#pragma unroll
        for (int wv = 0; wv < 8; wv++) {
            u64 m00p, m01p;
            GATE_M(wv, wv, m00p, m01p);
            float r0, i0, r1, i1;
            upk(m00p, r0, i0); upk(m01p, r1, i1);
            g0r[wv] = r0;  g0i[wv] = i0;
            g1r[wv] = -r1; g1i[wv] = i1;
        }
        float cr = 1.7724538509055159f, ci = 0.f;   // sqrt(pi) folded in
#pragma unroll
        for (int wv = 0; wv < 4; wv++) {
            bool b = (hl >> (3 - wv)) & 1;
            float fr = b ? g1r[wv] : g0r[wv];
            float fi = b ? g1i[wv] : g0i[wv];
            float nr = cr * fr - ci * fi;
            float ni = cr * fi + ci * fr;
            cr = nr; ci = ni;
        }
        // expand register wires 4,5,6,7 into 16 amps
        float d0r = cr * g0r[4] - ci * g0i[4], d0i = cr * g0i[4] + ci * g0r[4];
        float d1r = cr * g1r[4] - ci * g1i[4], d1i = cr * g1i[4] + ci * g1r[4];
        float er[4], ei[4];
        er[0] = d0r * g0r[5] - d0i * g0i[5]; ei[0] = d0r * g0i[5] + d0i * g0r[5];
        er[1] = d0r * g1r[5] - d0i * g1i[5]; ei[1] = d0r * g1i[5] + d0i * g1r[5];
        er[2] = d1r * g0r[5] - d1i * g0i[5]; ei[2] = d1r * g0i[5] + d1i * g0r[5];
        er[3] = d1r * g1r[5] - d1i * g1i[5]; ei[3] = d1r * g1i[5] + d1i * g1r[5];
        float fr8[8], fi8[8];
#pragma unroll
        for (int k = 0; k < 4; k++) {
            fr8[2*k]   = er[k] * g0r[6] - ei[k] * g0i[6];
            fi8[2*k]   = er[k] * g0i[6] + ei[k] * g0r[6];
            fr8[2*k+1] = er[k] * g1r[6] - ei[k] * g1i[6];
            fi8[2*k+1] = er[k] * g1i[6] + ei[k] * g1r[6];
        }
#pragma unroll
        for (int j = 0; j < 8; j++) {
            float alr = fr8[j] * g0r[7] - fi8[j] * g0i[7];
            float ali = fr8[j] * g0i[7] + fi8[j] * g0r[7];
            float ahr = fr8[j] * g1r[7] - fi8[j] * g1i[7];
            float ahi = fr8[j] * g1i[7] + fi8[j] * g1r[7];
            pr[j] = pk(alr, ahr);
            pi[j] = pk(ali, ahi);
        }
        // layer-0 lane perm (standalone)
#pragma unroll
        for (int j = 0; j < 8; j++) {
            pr[j] = shfi(pr[j], srcF);
            pi[j] = shfi(pi[j], srcF);
        }
    }

    // register-level CNOT tail: (3,4) predicated, (4,5)&(5,6) renames, (6,7) half-swap
#define REG_CNOTS()                                                          \
    {                                                                        \
        _Pragma("unroll")                                                    \
        for (int k = 0; k < 4; k++) {                                        \
            u64 a = pr[k], b = pr[k + 4];                                    \
            pr[k] = ctl34 ? b : a; pr[k + 4] = ctl34 ? a : b;                \
            u64 c = pi[k], d = pi[k + 4];                                    \
            pi[k] = ctl34 ? d : c; pi[k + 4] = ctl34 ? c : d;                \
        }                                                                    \
        { u64 t_;                                                            \
          t_ = pr[4]; pr[4] = pr[6]; pr[6] = t_;                             \
          t_ = pi[4]; pi[4] = pi[6]; pi[6] = t_;                             \
          t_ = pr[5]; pr[5] = pr[7]; pr[7] = t_;                             \
          t_ = pi[5]; pi[5] = pi[7]; pi[7] = t_; }                           \
        { u64 t_;                                                            \
          t_ = pr[2]; pr[2] = pr[3]; pr[3] = t_;                             \
          t_ = pi[2]; pi[2] = pi[3]; pi[3] = t_;                             \
          t_ = pr[6]; pr[6] = pr[7]; pr[7] = t_;                             \
          t_ = pi[6]; pi[6] = pi[7]; pi[7] = t_; }                           \
        pr[1] = swp(pr[1]); pr[3] = swp(pr[3]);                              \
        pr[5] = swp(pr[5]); pr[7] = swp(pr[7]);                              \
        pi[1] = swp(pi[1]); pi[3] = swp(pi[3]);                              \
        pi[5] = swp(pi[5]); pi[7] = swp(pi[7]);                              \
    }

    REG_CNOTS();

    // ---------- layers 1..5 ----------
#pragma unroll
    for (int layer = 1; layer < 6; layer++) {
#pragma unroll
        for (int wire = 0; wire < 8; wire++) {
            u64 m00p, m01p;
            GATE_M(layer * 8 + wire, wire, m00p, m01p);
            float m00r, m00i, m01r, m01i;
            upk(m00p, m00r, m00i); upk(m01p, m01r, m01i);

            if (wire < 3) {
                // lane-level butterfly via shfl.xor (within half-warp)
                const int lm = 8 >> wire;
                bool neg = (hl & lm) != 0;
                float Piv = neg ? -m00i : m00i;
                float Qrv = neg ? -m01r : m01r;
                u64 Pr2 = pk2(m00r), Pi2 = pk2(Piv), nPi2 = pk2(-Piv);
                u64 Qr2 = pk2(Qrv), Qi2 = pk2(m01i), nQi2 = pk2(-m01i);
#pragma unroll
                for (int j = 0; j < 8; j++) {
                    u64 opr = shfx(pr[j], lm);
                    u64 opi = shfx(pi[j], lm);
                    u64 nr = fma2(Pr2, pr[j], fma2(nPi2, pi[j], fma2(Qr2, opr, mul2(nQi2, opi))));
                    u64 ni = fma2(Pi2, pr[j], fma2(Pr2, pi[j], fma2(Qi2, opr, mul2(Qr2, opi))));
                    pr[j] = nr; pi[j] = ni;
                }
            } else if (wire == 3) {
                // wire-3 gate FUSED with the lane CNOT perm (perm commutes with
                // the register-local wires 4..7 gates).
                float Piv = negf ? -m00i : m00i;
                float Qrv = negf ? -m01r : m01r;
                u64 Pr2 = pk2(m00r), Pi2 = pk2(Piv), nPi2 = pk2(-Piv);
                u64 Qr2 = pk2(Qrv), Qi2 = pk2(m01i), nQi2 = pk2(-m01i);
#pragma unroll
                for (int j = 0; j < 8; j++) {
                    u64 ar = shfi(pr[j], srcF);
                    u64 ai = shfi(pi[j], srcF);
                    u64 br = shfi(pr[j], srcF2);
                    u64 bi = shfi(pi[j], srcF2);
                    u64 nr = fma2(Pr2, ar, fma2(nPi2, ai, fma2(Qr2, br, mul2(nQi2, bi))));
                    u64 ni = fma2(Pi2, ar, fma2(Pr2, ai, fma2(Qi2, br, mul2(Qr2, bi))));
                    pr[j] = nr; pi[j] = ni;
                }
            } else if (wire < 7) {
                // inter-register butterfly: wire4 off=4, wire5 off=2, wire6 off=1
                u64 r00 = pk2(m00r), i00 = pk2(m00i), ni00 = pk2(-m00i);
                u64 r01 = pk2(m01r), nr01 = pk2(-m01r), i01 = pk2(m01i), ni01 = pk2(-m01i);
                const int off = (wire == 4) ? 4 : ((wire == 5) ? 2 : 1);
#pragma unroll
                for (int j = 0; j < 8; j++) {
                    if (j & off) continue;
                    int k = j | off;
                    u64 pA = pr[j], qA = pi[j], pB = pr[k], qB = pi[k];
                    pr[j] = fma2(r00, pA, fma2(ni00, qA, fma2(r01, pB, mul2(ni01, qB))));
                    pi[j] = fma2(i00, pA, fma2(r00, qA, fma2(i01, pB, mul2(r01, qB))));
                    pr[k] = fma2(nr01, pA, fma2(ni01, qA, fma2(r00, pB, mul2(i00, qB))));
                    pi[k] = fma2(i01, pA, fma2(nr01, qA, fma2(ni00, pB, mul2(r00, qB))));
                }
            } else {
                // wire7: intra-register butterfly with half-swaps
                u64 A = pk2(m00r);
                u64 Bc = pk(m01r, -m01r);
                u64 Cc = pk(-m00i, m00i);
                u64 D = pk2(-m01i);
                u64 E = pk(m00i, -m00i);
                u64 F = pk2(m01i);
#pragma unroll
                for (int j = 0; j < 8; j++) {
                    u64 spr = swp(pr[j]), spi = swp(pi[j]);
                    u64 nr = fma2(A, pr[j], fma2(Bc, spr, fma2(Cc, pi[j], mul2(D, spi))));
                    u64 ni = fma2(E, pr[j], fma2(F, spr, fma2(A, pi[j], mul2(Bc, spi))));
                    pr[j] = nr; pi[j] = ni;
                }
            }
        }
        REG_CNOTS();
    }

    // ---------- expectation values (pre-scaled by pi), packed u64 trees ----------
    u64 q[8];
#pragma unroll
    for (int j = 0; j < 8; j++)
        q[j] = fma2(pr[j], pr[j], mul2(pi[j], pi[j]));

    // pairwise trees (j bit2 = wire4, bit1 = wire5, bit0 = wire6; half = wire7)
    u64 t01 = add2(q[0], q[1]), t23 = add2(q[2], q[3]);
    u64 t45 = add2(q[4], q[5]), t67 = add2(q[6], q[7]);
    u64 A4 = add2(t01, t23), B4 = add2(t45, t67);
    u64 S  = add2(A4, B4);                        // grand packed sum
    u64 D4 = sub2(A4, B4);                        // wire4 sign (j bit2)
    u64 D5 = sub2(add2(t01, t45), add2(t23, t67)); // wire5 sign (j bit1)
    u64 D6 = add2(add2(sub2(q[0], q[1]), sub2(q[2], q[3])),
                  add2(sub2(q[4], q[5]), sub2(q[6], q[7]))); // wire6 (j bit0)

    float sl, sh, d4l, d4h, d5l, d5h, d6l, d6h;
    upk(S, sl, sh); upk(D4, d4l, d4h); upk(D5, d5l, d5h); upk(D6, d6l, d6h);
    float tot = sl + sh;                 // total probability (pi-scaled)
    u64 e45 = pk(d4l + d4h, d5l + d5h);  // (ev4, ev5) packed
    u64 e67 = pk(d6l + d6h, sl - sh);    // (ev6, ev7) packed

    // 4-step Walsh-Hadamard on tot within the half-warp: X(k) at hl=k;
    // ev_i (wires 0..3) = X(1<<(3-i)). Packed plain-add butterflies for ev4..7.
#pragma unroll
    for (int b = 0; b < 4; b++) {
        const int m = 1 << b;
        float o = __shfl_xor_sync(FULL, tot, m);
        tot = (lane & m) ? (o - tot) : (o + tot);
        e45 = add2(e45, shfx(e45, m));
        e67 = add2(e67, shfx(e67, m));
    }

    float* o = out + elem * 8;
    if (hl == 8) o[0] = tot;
    if (hl == 4) o[1] = tot;
    if (hl == 2) o[2] = tot;
    if (hl == 1) o[3] = tot;
    if (hl == 0) {
        float a4, a5, a6, a7;
        upk(e45, a4, a5); upk(e67, a6, a7);
        o[4] = a4;
        o[5] = a5;
        o[6] = a6;
        o[7] = a7;
    }
#undef GATE_M
#undef REG_CNOTS
}

extern "C" void kernel_launch(void* const* d_in, const int* in_sizes, int n_in,
                              void* d_out, int out_size) {
    const float* x = (const float*)d_in[0];   // [B, 2]
    const float* w = (const float*)d_in[1];   // [6, 8, 3]
    float* out = (float*)d_out;               // [B, 8]
    int B = in_sizes[0] / 2;
    int NE2 = B / 2;                          // warps (2 elements per warp)

    precompute_G<<<1, 64>>>(w);
    int threads = 128;
    int blocks = (NE2 * 32 + threads - 1) / threads;
    qnn_kernel<<<blocks, threads>>>((const float2*)x, out, NE2);
}